// round 6
// baseline (speedup 1.0000x reference)
#include <cuda_runtime.h>
#include <math.h>
#include <stdint.h>

// ---------------- problem constants ----------------
#define DM      4096
#define MROWS   8192          // B*N = 4*2048
#define IB      1024          // block size (DM / 4 blocks)
#define DFF     5461
#define EPSD    1e-5

typedef unsigned long long u64;

// ---------------- scratch (device globals; no allocations allowed) ----------
__device__ float  g_xa[(size_t)MROWS * DM];        // 128 MB silu(x)
__device__ float  g_pre[4ULL * MROWS * DM];        // 512 MB gate pre-activations
__device__ float  g_lnct[(size_t)MROWS * DM];      // 128 MB LN(i*z) values
__device__ float  g_lni[(size_t)MROWS * DM];       // 128 MB LN(i) values
__device__ float  g_obuf[(size_t)MROWS * DM];      // 128 MB o-gate values
__device__ float  g_ratio[DM];                     // ct/nt (fp32, ref-matched)
__device__ double g_htmsum[DM];
__device__ double g_s[DM];                         // slstm_out
__device__ double g_v[DFF];                        // left*right (pre-LN)
__device__ double g_u[DFF];                        // LN'd

// ---------------- XLA-matched elementwise math ----------------
__device__ __forceinline__ float tanh_xla(float x) {
    const float kMax = 7.90531110763549805f;
    float cx = fminf(fmaxf(x, -kMax), kMax);
    float x2 = __fmul_rn(cx, cx);
    float p = fmaf(x2, -2.76076847742355e-16f, 2.00018790482477e-13f);
    p = fmaf(p, x2, -8.60467152213735e-11f);
    p = fmaf(p, x2, 5.12229709037114e-08f);
    p = fmaf(p, x2, 1.48572235717979e-05f);
    p = fmaf(p, x2, 6.37261928875436e-04f);
    p = fmaf(p, x2, 4.89352455891786e-03f);
    p = __fmul_rn(cx, p);
    float q = fmaf(x2, 1.19825839466702e-06f, 1.18534705686654e-04f);
    q = fmaf(q, x2, 2.26843463243900e-03f);
    q = fmaf(q, x2, 4.89352518554385e-03f);
    float r = __fdiv_rn(p, q);
    return (fabsf(x) < 0.0004f) ? x : r;
}

__device__ __forceinline__ float logistic_xla(float x) {
    return fmaf(0.5f, tanh_xla(__fmul_rn(0.5f, x)), 0.5f);
}

__device__ __forceinline__ float silu_xla(float x) {
    return __fmul_rn(x, logistic_xla(x));
}

// ---------------- packed fp32 FMA (Blackwell f32x2; each half is rn-exact) --
__device__ __forceinline__ void ffma2(u64& d, u64 a, u64 b) {
    asm("fma.rn.f32x2 %0, %1, %2, %0;" : "+l"(d) : "l"(a), "l"(b));
}
__device__ __forceinline__ u64 pack2(float lo, float hi) {
    u64 r;
    asm("mov.b64 %0, {%1, %2};" : "=l"(r) : "f"(lo), "f"(hi));
    return r;
}
__device__ __forceinline__ void unpack2(u64 v, float& lo, float& hi) {
    asm("mov.b64 {%0, %1}, %2;" : "=f"(lo), "=f"(hi) : "l"(v));
}

// ---------------- fp64 block reduce ----------------
template <int NV>
__device__ __forceinline__ void block_reduce_d(double* v, double* sred) {
    const int lane = threadIdx.x & 31;
    const int wid  = threadIdx.x >> 5;
    const int nw   = (blockDim.x + 31) >> 5;
#pragma unroll
    for (int i = 0; i < NV; ++i) {
        double x = v[i];
#pragma unroll
        for (int o = 16; o > 0; o >>= 1) x += __shfl_xor_sync(0xffffffffu, x, o);
        v[i] = x;
    }
    __syncthreads();
    if (lane == 0) {
#pragma unroll
        for (int i = 0; i < NV; ++i) sred[wid * NV + i] = v[i];
    }
    __syncthreads();
    if (wid == 0) {
#pragma unroll
        for (int i = 0; i < NV; ++i) {
            double x = (lane < nw) ? sred[lane * NV + i] : 0.0;
#pragma unroll
            for (int o = 16; o > 0; o >>= 1) x += __shfl_xor_sync(0xffffffffu, x, o);
            if (lane == 0) sred[i] = x;
        }
    }
    __syncthreads();
#pragma unroll
    for (int i = 0; i < NV; ++i) v[i] = sred[i];
    __syncthreads();
}

// ---------------- kernel: zero + silu ----------------
__global__ void k_zero() {
    int idx = blockIdx.x * blockDim.x + threadIdx.x;
    if (idx < DM) g_htmsum[idx] = 0.0;
}

__global__ __launch_bounds__(256) void k_silu(const float* __restrict__ x) {
    size_t i = ((size_t)blockIdx.x * 256 + threadIdx.x) * 4;
    float4 v = *(const float4*)(x + i);
    v.x = silu_xla(v.x); v.y = silu_xla(v.y); v.z = silu_xla(v.z); v.w = silu_xla(v.w);
    *(float4*)(g_xa + i) = v;
}

// ---------------- kernel: fp32 SGEMM via f32x2, ascending-k chains ----------
// pre[g][row][blk*1024 + o] = sum_k xa[row][blk*1024+k] * W[g][blk][o][k]
// Bit-exact to scalar fmaf chains: each f32x2 half is an independent rn FMA;
// per-output-element accumulation order (ascending k, single accumulator)
// is unchanged — pairing is across output columns only.
__global__ __launch_bounds__(256, 2) void k_gemm(const float* __restrict__ Wg) {
    __shared__ __align__(16) float As[2][16 * 132];
    __shared__ __align__(16) float Bs[2][16 * 132];

    const int mtile = blockIdx.x;
    const int ntile = blockIdx.y;
    const int g     = blockIdx.z & 3;
    const int blk   = blockIdx.z >> 2;

    const int tid = threadIdx.x;
    const int tx  = tid & 15;        // o-group
    const int ty  = tid >> 4;        // row-group
    const int rb  = ty * 8;
    const int ob  = tx * 8;

    const float* aBase = g_xa + (size_t)(mtile * 128) * DM + blk * IB;
    const float* bBase = Wg + ((size_t)(g * 4 + blk)) * IB * IB + (size_t)(ntile * 128) * IB;

    const int s0 = tid, s1 = tid + 256;
    const int ar0 = s0 >> 2, aq0 = (s0 & 3) * 4;
    const int ar1 = s1 >> 2, aq1 = (s1 & 3) * 4;

    u64 acc[8][4];
#pragma unroll
    for (int i = 0; i < 8; ++i)
#pragma unroll
        for (int j = 0; j < 4; ++j) acc[i][j] = 0ull;   // {0.f, 0.f}

    float4 pa0, pa1, pb0, pb1;
    pa0 = *(const float4*)(aBase + (size_t)ar0 * DM + aq0);
    pa1 = *(const float4*)(aBase + (size_t)ar1 * DM + aq1);
    pb0 = *(const float4*)(bBase + (size_t)ar0 * IB + aq0);
    pb1 = *(const float4*)(bBase + (size_t)ar1 * IB + aq1);
    {
        float* A = As[0]; float* B = Bs[0];
        A[(aq0 + 0) * 132 + ar0] = pa0.x; A[(aq0 + 1) * 132 + ar0] = pa0.y;
        A[(aq0 + 2) * 132 + ar0] = pa0.z; A[(aq0 + 3) * 132 + ar0] = pa0.w;
        A[(aq1 + 0) * 132 + ar1] = pa1.x; A[(aq1 + 1) * 132 + ar1] = pa1.y;
        A[(aq1 + 2) * 132 + ar1] = pa1.z; A[(aq1 + 3) * 132 + ar1] = pa1.w;
        B[(aq0 + 0) * 132 + ar0] = pb0.x; B[(aq0 + 1) * 132 + ar0] = pb0.y;
        B[(aq0 + 2) * 132 + ar0] = pb0.z; B[(aq0 + 3) * 132 + ar0] = pb0.w;
        B[(aq1 + 0) * 132 + ar1] = pb1.x; B[(aq1 + 1) * 132 + ar1] = pb1.y;
        B[(aq1 + 2) * 132 + ar1] = pb1.z; B[(aq1 + 3) * 132 + ar1] = pb1.w;
    }
    __syncthreads();

#pragma unroll 1
    for (int kt = 0; kt < 64; ++kt) {
        const int cur = kt & 1;
        if (kt < 63) {
            const int k0 = (kt + 1) * 16;
            pa0 = *(const float4*)(aBase + (size_t)ar0 * DM + k0 + aq0);
            pa1 = *(const float4*)(aBase + (size_t)ar1 * DM + k0 + aq1);
            pb0 = *(const float4*)(bBase + (size_t)ar0 * IB + k0 + aq0);
            pb1 = *(const float4*)(bBase + (size_t)ar1 * IB + k0 + aq1);
        }
        const float* A = As[cur];
        const float* B = Bs[cur];
#pragma unroll
        for (int k = 0; k < 16; ++k) {
            float4 a0 = *(const float4*)(A + k * 132 + rb);
            float4 a1 = *(const float4*)(A + k * 132 + rb + 4);
            float4 b0 = *(const float4*)(B + k * 132 + ob);
            float4 b1 = *(const float4*)(B + k * 132 + ob + 4);
            u64 bu[4];
            bu[0] = pack2(b0.x, b0.y); bu[1] = pack2(b0.z, b0.w);
            bu[2] = pack2(b1.x, b1.y); bu[3] = pack2(b1.z, b1.w);
            float av[8] = {a0.x, a0.y, a0.z, a0.w, a1.x, a1.y, a1.z, a1.w};
#pragma unroll
            for (int i = 0; i < 8; ++i) {
                u64 ap = pack2(av[i], av[i]);
#pragma unroll
                for (int j = 0; j < 4; ++j) ffma2(acc[i][j], ap, bu[j]);
            }
        }
        if (kt < 63) {
            float* An = As[cur ^ 1]; float* Bn = Bs[cur ^ 1];
            An[(aq0 + 0) * 132 + ar0] = pa0.x; An[(aq0 + 1) * 132 + ar0] = pa0.y;
            An[(aq0 + 2) * 132 + ar0] = pa0.z; An[(aq0 + 3) * 132 + ar0] = pa0.w;
            An[(aq1 + 0) * 132 + ar1] = pa1.x; An[(aq1 + 1) * 132 + ar1] = pa1.y;
            An[(aq1 + 2) * 132 + ar1] = pa1.z; An[(aq1 + 3) * 132 + ar1] = pa1.w;
            Bn[(aq0 + 0) * 132 + ar0] = pb0.x; Bn[(aq0 + 1) * 132 + ar0] = pb0.y;
            Bn[(aq0 + 2) * 132 + ar0] = pb0.z; Bn[(aq0 + 3) * 132 + ar0] = pb0.w;
            Bn[(aq1 + 0) * 132 + ar1] = pb1.x; Bn[(aq1 + 1) * 132 + ar1] = pb1.y;
            Bn[(aq1 + 2) * 132 + ar1] = pb1.z; Bn[(aq1 + 3) * 132 + ar1] = pb1.w;
            __syncthreads();
        }
    }

    float* C = g_pre + (size_t)g * MROWS * DM + (size_t)blk * IB + (size_t)(ntile * 128) + ob;
#pragma unroll
    for (int i = 0; i < 8; ++i) {
        const size_t row = (size_t)(mtile * 128 + rb + i);
        float c0, c1, c2, c3, c4, c5, c6, c7;
        unpack2(acc[i][0], c0, c1);
        unpack2(acc[i][1], c2, c3);
        unpack2(acc[i][2], c4, c5);
        unpack2(acc[i][3], c6, c7);
        *(float4*)(C + row * DM)     = make_float4(c0, c1, c2, c3);
        *(float4*)(C + row * DM + 4) = make_float4(c4, c5, c6, c7);
    }
}

// ---------------- kernel: row-wise gates (stats fp64, values fp32) ----------
__global__ __launch_bounds__(512) void k_pass2(const float* __restrict__ b_gates,
                                               const float* __restrict__ lng,
                                               const float* __restrict__ lnb) {
    __shared__ double s_red[16 * 8];
    const int tid = threadIdx.x;
    const int d0 = tid * 8;

    for (int row = blockIdx.x; row < MROWS; row += gridDim.x) {
        float p[4][8];
#pragma unroll
        for (int gg = 0; gg < 4; ++gg) {
            const float* base = g_pre + ((size_t)gg * MROWS + row) * DM + d0;
            float4 u = *(const float4*)(base);
            float4 v = *(const float4*)(base + 4);
            const float* bg = b_gates + gg * DM + d0;
            float4 w = *(const float4*)(bg);
            float4 y = *(const float4*)(bg + 4);
            p[gg][0] = __fadd_rn(u.x, w.x); p[gg][1] = __fadd_rn(u.y, w.y);
            p[gg][2] = __fadd_rn(u.z, w.z); p[gg][3] = __fadd_rn(u.w, w.w);
            p[gg][4] = __fadd_rn(v.x, y.x); p[gg][5] = __fadd_rn(v.y, y.y);
            p[gg][6] = __fadd_rn(v.z, y.z); p[gg][7] = __fadd_rn(v.w, y.w);
        }
        double v8[8];
#pragma unroll
        for (int gg = 0; gg < 4; ++gg) {
            double s = 0.0, q = 0.0;
#pragma unroll
            for (int c = 0; c < 8; ++c) {
                double pv = (double)p[gg][c];
                s += pv; q += pv * pv;
            }
            v8[2 * gg] = s; v8[2 * gg + 1] = q;
        }
        block_reduce_d<8>(v8, s_red);
        double mu[4], rs[4];
#pragma unroll
        for (int gg = 0; gg < 4; ++gg) {
            mu[gg] = v8[2 * gg] * (1.0 / DM);
            double var = v8[2 * gg + 1] * (1.0 / DM) - mu[gg] * mu[gg];
            rs[gg] = 1.0 / sqrt(var + EPSD);
        }
        float iv[8], cv[8], ov[8];
#pragma unroll
        for (int c = 0; c < 8; ++c) {
            const int d = d0 + c;
            float li = (float)((((double)p[0][c] - mu[0]) * rs[0]) * (double)lng[d]          + (double)lnb[d]);
            float lf = (float)((((double)p[1][c] - mu[1]) * rs[1]) * (double)lng[DM + d]     + (double)lnb[DM + d]);
            float lo = (float)((((double)p[2][c] - mu[2]) * rs[2]) * (double)lng[2 * DM + d] + (double)lnb[2 * DM + d]);
            float lz = (float)((((double)p[3][c] - mu[3]) * rs[3]) * (double)lng[3 * DM + d] + (double)lnb[3 * DM + d]);
            float m  = fmaxf(li, lf);
            float q  = __fadd_rn(li, -m);
            float ii = (float)exp((double)q);        // near-correctly-rounded f32 exp
            float zz = tanh_xla(lz);
            ov[c] = logistic_xla(lo);
            iv[c] = ii;
            cv[c] = __fmul_rn(ii, zz);
        }
        {
            float* ob = g_obuf + (size_t)row * DM + d0;
            *(float4*)(ob)     = make_float4(ov[0], ov[1], ov[2], ov[3]);
            *(float4*)(ob + 4) = make_float4(ov[4], ov[5], ov[6], ov[7]);
        }
        double v4[4] = {0.0, 0.0, 0.0, 0.0};
#pragma unroll
        for (int c = 0; c < 8; ++c) {
            double cd = (double)cv[c], id = (double)iv[c];
            v4[0] += cd; v4[1] += cd * cd;
            v4[2] += id; v4[3] += id * id;
        }
        block_reduce_d<4>(v4, s_red);
        const double muc = v4[0] * (1.0 / DM);
        const double rsc = 1.0 / sqrt(v4[1] * (1.0 / DM) - muc * muc + EPSD);
        const double mui = v4[2] * (1.0 / DM);
        const double rsi = 1.0 / sqrt(v4[3] * (1.0 / DM) - mui * mui + EPSD);
        float lc[8], ln_[8];
#pragma unroll
        for (int c = 0; c < 8; ++c) {
            const int d = d0 + c;
            lc[c]  = (float)((((double)cv[c] - muc) * rsc) * (double)lng[4 * DM + d] + (double)lnb[4 * DM + d]);
            ln_[c] = (float)((((double)iv[c] - mui) * rsi) * (double)lng[5 * DM + d] + (double)lnb[5 * DM + d]);
        }
        float* pc = g_lnct + (size_t)row * DM + d0;
        float* pn = g_lni + (size_t)row * DM + d0;
        *(float4*)(pc)     = make_float4(lc[0], lc[1], lc[2], lc[3]);
        *(float4*)(pc + 4) = make_float4(lc[4], lc[5], lc[6], lc[7]);
        *(float4*)(pn)     = make_float4(ln_[0], ln_[1], ln_[2], ln_[3]);
        *(float4*)(pn + 4) = make_float4(ln_[4], ln_[5], ln_[6], ln_[7]);
    }
}

// ---------------- kernel: SEQUENTIAL ascending-row fp32 column sums ---------
__global__ __launch_bounds__(32) void k_redsum() {
    const int d = blockIdx.x * 32 + threadIdx.x;
    const float* pc = g_lnct + d;
    const float* pn = g_lni + d;
    float ac = 0.0f, an = 0.0f;
#pragma unroll 16
    for (int row = 0; row < MROWS; ++row) {
        ac = __fadd_rn(ac, __ldg(pc + (size_t)row * DM));
        an = __fadd_rn(an, __ldg(pn + (size_t)row * DM));
    }
    const float cm = __fmul_rn(ac, 1.0f / MROWS);
    const float nm = __fmul_rn(an, 1.0f / MROWS);
    g_ratio[d] = __fdiv_rn(cm, nm);
}

// ---------------- kernel: ht pass (non-amplified; fp64 stats) ----------------
__global__ __launch_bounds__(512) void k_pass3(const float* __restrict__ lng,
                                               const float* __restrict__ lnb) {
    __shared__ double s_htm[DM];
    __shared__ double s_red[16 * 2];
    const int tid = threadIdx.x;
    for (int d = tid; d < DM; d += 512) s_htm[d] = 0.0;
    __syncthreads();
    const int d0 = tid * 8;
    float rr[8];
#pragma unroll
    for (int c = 0; c < 8; ++c) rr[c] = g_ratio[d0 + c];

    for (int row = blockIdx.x; row < MROWS; row += gridDim.x) {
        const float* ob = g_obuf + (size_t)row * DM + d0;
        float4 u = *(const float4*)(ob);
        float4 v = *(const float4*)(ob + 4);
        float h[8] = {__fmul_rn(u.x, rr[0]), __fmul_rn(u.y, rr[1]),
                      __fmul_rn(u.z, rr[2]), __fmul_rn(u.w, rr[3]),
                      __fmul_rn(v.x, rr[4]), __fmul_rn(v.y, rr[5]),
                      __fmul_rn(v.z, rr[6]), __fmul_rn(v.w, rr[7])};
        double v2[2] = {0.0, 0.0};
#pragma unroll
        for (int c = 0; c < 8; ++c) { double hd = (double)h[c]; v2[0] += hd; v2[1] += hd * hd; }
        block_reduce_d<2>(v2, s_red);
        const double mu = v2[0] * (1.0 / DM);
        const double rs = 1.0 / sqrt(v2[1] * (1.0 / DM) - mu * mu + EPSD);
#pragma unroll
        for (int c = 0; c < 8; ++c) {
            const int d = d0 + c;
            s_htm[d] += ((double)h[c] - mu) * rs * (double)lng[6 * DM + d] + (double)lnb[6 * DM + d];
        }
    }
    __syncthreads();
    for (int d = tid; d < DM; d += 512) atomicAdd(&g_htmsum[d], s_htm[d]);
}

// ---------------- kernel: slstm_out = LN(mean ht) (fp64) ----------------
__global__ __launch_bounds__(512) void k_pass4(const float* __restrict__ lng,
                                               const float* __restrict__ lnb) {
    __shared__ double s_red[16 * 2];
    const int tid = threadIdx.x;
    const int d0 = tid * 8;
    double h[8];
#pragma unroll
    for (int c = 0; c < 8; ++c) h[c] = g_htmsum[d0 + c] * (1.0 / MROWS);
    double v2[2] = {0.0, 0.0};
#pragma unroll
    for (int c = 0; c < 8; ++c) { v2[0] += h[c]; v2[1] += h[c] * h[c]; }
    block_reduce_d<2>(v2, s_red);
    const double mu = v2[0] * (1.0 / DM);
    const double rs = 1.0 / sqrt(v2[1] * (1.0 / DM) - mu * mu + EPSD);
#pragma unroll
    for (int c = 0; c < 8; ++c) {
        const int d = d0 + c;
        g_s[d] = (h[c] - mu) * rs * (double)lng[7 * DM + d] + (double)lnb[7 * DM + d];
    }
}

// ---------------- kernel: left/right GEMVs + gelu + product (fp64) ----------
__global__ __launch_bounds__(128) void k_pass5(const float* __restrict__ Wl,
                                               const float* __restrict__ bl,
                                               const float* __restrict__ Wr,
                                               const float* __restrict__ br) {
    __shared__ double s_red[4 * 2];
    const int j = blockIdx.x;
    const int tid = threadIdx.x;
    double v2[2] = {0.0, 0.0};
    const float* wl = Wl + (size_t)j * DM;
    const float* wr = Wr + (size_t)j * DM;
    for (int d = tid; d < DM; d += 128) {
        const double s = g_s[d];
        v2[0] += s * (double)wl[d];
        v2[1] += s * (double)wr[d];
    }
    block_reduce_d<2>(v2, s_red);
    if (tid == 0) {
        const double left = v2[0] + (double)bl[j];
        double right = v2[1] + (double)br[j];
        right = 0.5 * right * (1.0 + erf(right * 0.7071067811865475244));  // exact gelu
        g_v[j] = left * right;
    }
}

// ---------------- kernel: LN over DFF (fp64) ----------------
__global__ __launch_bounds__(512) void k_pass6a(const float* __restrict__ og,
                                                const float* __restrict__ ob) {
    __shared__ double s_red[16 * 2];
    const int tid = threadIdx.x;
    double v2[2] = {0.0, 0.0};
    for (int jj = tid; jj < DFF; jj += 512) {
        const double x = g_v[jj];
        v2[0] += x; v2[1] += x * x;
    }
    block_reduce_d<2>(v2, s_red);
    const double mu = v2[0] * (1.0 / DFF);
    const double rs = 1.0 / sqrt(v2[1] * (1.0 / DFF) - mu * mu + EPSD);
    for (int jj = tid; jj < DFF; jj += 512)
        g_u[jj] = (g_v[jj] - mu) * rs * (double)og[jj] + (double)ob[jj];
}

// ---------------- kernel: final projection GEMV (fp64) ----------------
__global__ __launch_bounds__(128) void k_pass6b(const float* __restrict__ Wp,
                                                const float* __restrict__ bp,
                                                float* __restrict__ out) {
    __shared__ double s_red[4 * 1];
    const int d = blockIdx.x;
    const int tid = threadIdx.x;
    double acc[1] = {0.0};
    const float* wp = Wp + (size_t)d * DFF;
    for (int jj = tid; jj < DFF; jj += 128) acc[0] += g_u[jj] * (double)wp[jj];
    block_reduce_d<1>(acc, s_red);
    if (tid == 0) out[d] = (float)(acc[0] + (double)bp[d]);
}

// ---------------- launcher ----------------
extern "C" void kernel_launch(void* const* d_in, const int* in_sizes, int n_in,
                              void* d_out, int out_size) {
    const float* x      = (const float*)d_in[0];
    const float* Wg     = (const float*)d_in[1];
    const float* bgates = (const float*)d_in[2];
    // d_in[3] = Wr_gates: multiplies zero initial state -> unused
    const float* lng    = (const float*)d_in[4];
    const float* lnb    = (const float*)d_in[5];
    const float* lnoutg = (const float*)d_in[6];
    const float* lnoutb = (const float*)d_in[7];
    const float* Wl     = (const float*)d_in[8];
    const float* bl     = (const float*)d_in[9];
    const float* Wr     = (const float*)d_in[10];
    const float* br     = (const float*)d_in[11];
    const float* Wp     = (const float*)d_in[12];
    const float* bp     = (const float*)d_in[13];
    float* out = (float*)d_out;

    k_zero<<<8, 512>>>();
    k_silu<<<(MROWS * (size_t)DM) / (256 * 4), 256>>>(x);
    k_gemm<<<dim3(64, 8, 16), 256>>>(Wg);
    k_pass2<<<296, 512>>>(bgates, lng, lnb);
    k_redsum<<<DM / 32, 32>>>();
    k_pass3<<<296, 512>>>(lng, lnb);
    k_pass4<<<1, 512>>>(lng, lnb);
    k_pass5<<<DFF, 128>>>(Wl, bl, Wr, br);
    k_pass6a<<<1, 512>>>(lnoutg, lnoutb);
    k_pass6b<<<DM, 128>>>(Wp, bp, out);
}

// round 7
// speedup vs baseline: 1.6747x; 1.6747x over previous
#include <cuda_runtime.h>
#include <math.h>
#include <stdint.h>

// ---------------- problem constants ----------------
#define DM      4096
#define MROWS   8192          // B*N = 4*2048
#define IB      1024          // block size (DM / 4 blocks)
#define DFF     5461
#define EPSD    1e-5

// ---------------- scratch (device globals; no allocations allowed) ----------
__device__ float  g_xa[(size_t)MROWS * DM];        // 128 MB silu(x)
__device__ float  g_pre[4ULL * MROWS * DM];        // 512 MB gate pre-activations
__device__ float  g_lnct[(size_t)MROWS * DM];      // 128 MB LN(i*z) values
__device__ float  g_lni[(size_t)MROWS * DM];       // 128 MB LN(i) values
__device__ float  g_obuf[(size_t)MROWS * DM];      // 128 MB o-gate values
__device__ float  g_ratio[DM];                     // ct/nt (fp32, ref-matched)
__device__ double g_htmsum[DM];
__device__ double g_s[DM];                         // slstm_out
__device__ double g_v[DFF];                        // left*right (pre-LN)
__device__ double g_u[DFF];                        // LN'd

// ---------------- XLA-matched elementwise math ----------------
__device__ __forceinline__ float tanh_xla(float x) {
    const float kMax = 7.90531110763549805f;
    float cx = fminf(fmaxf(x, -kMax), kMax);
    float x2 = __fmul_rn(cx, cx);
    float p = fmaf(x2, -2.76076847742355e-16f, 2.00018790482477e-13f);
    p = fmaf(p, x2, -8.60467152213735e-11f);
    p = fmaf(p, x2, 5.12229709037114e-08f);
    p = fmaf(p, x2, 1.48572235717979e-05f);
    p = fmaf(p, x2, 6.37261928875436e-04f);
    p = fmaf(p, x2, 4.89352455891786e-03f);
    p = __fmul_rn(cx, p);
    float q = fmaf(x2, 1.19825839466702e-06f, 1.18534705686654e-04f);
    q = fmaf(q, x2, 2.26843463243900e-03f);
    q = fmaf(q, x2, 4.89352518554385e-03f);
    float r = __fdiv_rn(p, q);
    return (fabsf(x) < 0.0004f) ? x : r;
}

__device__ __forceinline__ float logistic_xla(float x) {
    return fmaf(0.5f, tanh_xla(__fmul_rn(0.5f, x)), 0.5f);
}

__device__ __forceinline__ float silu_xla(float x) {
    return __fmul_rn(x, logistic_xla(x));
}

// ---------------- TF32 helpers ----------------
__device__ __forceinline__ float to_tf32(float v) {
    unsigned u;
    asm("cvt.rna.tf32.f32 %0, %1;" : "=r"(u) : "f"(v));
    return __uint_as_float(u);
}

__device__ __forceinline__ void mma_tf32(float4& d, const float* a, float b0, float b1) {
    asm volatile(
        "mma.sync.aligned.m16n8k8.row.col.f32.tf32.tf32.f32 "
        "{%0,%1,%2,%3}, {%4,%5,%6,%7}, {%8,%9}, {%0,%1,%2,%3};\n"
        : "+f"(d.x), "+f"(d.y), "+f"(d.z), "+f"(d.w)
        : "r"(__float_as_uint(a[0])), "r"(__float_as_uint(a[1])),
          "r"(__float_as_uint(a[2])), "r"(__float_as_uint(a[3])),
          "r"(__float_as_uint(b0)), "r"(__float_as_uint(b1)));
}

// ---------------- fp64 block reduce ----------------
template <int NV>
__device__ __forceinline__ void block_reduce_d(double* v, double* sred) {
    const int lane = threadIdx.x & 31;
    const int wid  = threadIdx.x >> 5;
    const int nw   = (blockDim.x + 31) >> 5;
#pragma unroll
    for (int i = 0; i < NV; ++i) {
        double x = v[i];
#pragma unroll
        for (int o = 16; o > 0; o >>= 1) x += __shfl_xor_sync(0xffffffffu, x, o);
        v[i] = x;
    }
    __syncthreads();
    if (lane == 0) {
#pragma unroll
        for (int i = 0; i < NV; ++i) sred[wid * NV + i] = v[i];
    }
    __syncthreads();
    if (wid == 0) {
#pragma unroll
        for (int i = 0; i < NV; ++i) {
            double x = (lane < nw) ? sred[lane * NV + i] : 0.0;
#pragma unroll
            for (int o = 16; o > 0; o >>= 1) x += __shfl_xor_sync(0xffffffffu, x, o);
            if (lane == 0) sred[i] = x;
        }
    }
    __syncthreads();
#pragma unroll
    for (int i = 0; i < NV; ++i) v[i] = sred[i];
    __syncthreads();
}

// ---------------- kernel: zero + silu ----------------
__global__ void k_zero() {
    int idx = blockIdx.x * blockDim.x + threadIdx.x;
    if (idx < DM) g_htmsum[idx] = 0.0;
}

__global__ __launch_bounds__(256) void k_silu(const float* __restrict__ x) {
    size_t i = ((size_t)blockIdx.x * 256 + threadIdx.x) * 4;
    float4 v = *(const float4*)(x + i);
    v.x = silu_xla(v.x); v.y = silu_xla(v.y); v.z = silu_xla(v.z); v.w = silu_xla(v.w);
    *(float4*)(g_xa + i) = v;
}

// ---------------- kernel: scalar fp32 SGEMM (gates i,f), ascending-k -------
// Bit-exact match of XLA's sgemm chains; only gates 0,1 feed the amplified
// denominator path. grid: x=mtile(64), y=ntile(8), z=blk*2+g (8), g in {0,1}.
__global__ __launch_bounds__(256, 2) void k_gemm_if(const float* __restrict__ Wg) {
    __shared__ __align__(16) float As[2][16 * 132];
    __shared__ __align__(16) float Bs[2][16 * 132];

    const int mtile = blockIdx.x;
    const int ntile = blockIdx.y;
    const int g     = blockIdx.z & 1;        // gate 0 or 1
    const int blk   = blockIdx.z >> 1;

    const int tid = threadIdx.x;
    const int tx  = tid & 15;
    const int ty  = tid >> 4;
    const int rb  = ty * 8;
    const int ob  = tx * 8;

    const float* aBase = g_xa + (size_t)(mtile * 128) * DM + blk * IB;
    const float* bBase = Wg + ((size_t)(g * 4 + blk)) * IB * IB + (size_t)(ntile * 128) * IB;

    const int s0 = tid, s1 = tid + 256;
    const int ar0 = s0 >> 2, aq0 = (s0 & 3) * 4;
    const int ar1 = s1 >> 2, aq1 = (s1 & 3) * 4;

    float acc[8][8];
#pragma unroll
    for (int i = 0; i < 8; ++i)
#pragma unroll
        for (int j = 0; j < 8; ++j) acc[i][j] = 0.0f;

    float4 pa0, pa1, pb0, pb1;
    pa0 = *(const float4*)(aBase + (size_t)ar0 * DM + aq0);
    pa1 = *(const float4*)(aBase + (size_t)ar1 * DM + aq1);
    pb0 = *(const float4*)(bBase + (size_t)ar0 * IB + aq0);
    pb1 = *(const float4*)(bBase + (size_t)ar1 * IB + aq1);
    {
        float* A = As[0]; float* B = Bs[0];
        A[(aq0 + 0) * 132 + ar0] = pa0.x; A[(aq0 + 1) * 132 + ar0] = pa0.y;
        A[(aq0 + 2) * 132 + ar0] = pa0.z; A[(aq0 + 3) * 132 + ar0] = pa0.w;
        A[(aq1 + 0) * 132 + ar1] = pa1.x; A[(aq1 + 1) * 132 + ar1] = pa1.y;
        A[(aq1 + 2) * 132 + ar1] = pa1.z; A[(aq1 + 3) * 132 + ar1] = pa1.w;
        B[(aq0 + 0) * 132 + ar0] = pb0.x; B[(aq0 + 1) * 132 + ar0] = pb0.y;
        B[(aq0 + 2) * 132 + ar0] = pb0.z; B[(aq0 + 3) * 132 + ar0] = pb0.w;
        B[(aq1 + 0) * 132 + ar1] = pb1.x; B[(aq1 + 1) * 132 + ar1] = pb1.y;
        B[(aq1 + 2) * 132 + ar1] = pb1.z; B[(aq1 + 3) * 132 + ar1] = pb1.w;
    }
    __syncthreads();

#pragma unroll 1
    for (int kt = 0; kt < 64; ++kt) {
        const int cur = kt & 1;
        if (kt < 63) {
            const int k0 = (kt + 1) * 16;
            pa0 = *(const float4*)(aBase + (size_t)ar0 * DM + k0 + aq0);
            pa1 = *(const float4*)(aBase + (size_t)ar1 * DM + k0 + aq1);
            pb0 = *(const float4*)(bBase + (size_t)ar0 * IB + k0 + aq0);
            pb1 = *(const float4*)(bBase + (size_t)ar1 * IB + k0 + aq1);
        }
        const float* A = As[cur];
        const float* B = Bs[cur];
#pragma unroll
        for (int k = 0; k < 16; ++k) {
            float4 a0 = *(const float4*)(A + k * 132 + rb);
            float4 a1 = *(const float4*)(A + k * 132 + rb + 4);
            float4 b0 = *(const float4*)(B + k * 132 + ob);
            float4 b1 = *(const float4*)(B + k * 132 + ob + 4);
            float av[8] = {a0.x, a0.y, a0.z, a0.w, a1.x, a1.y, a1.z, a1.w};
            float bv[8] = {b0.x, b0.y, b0.z, b0.w, b1.x, b1.y, b1.z, b1.w};
#pragma unroll
            for (int i = 0; i < 8; ++i)
#pragma unroll
                for (int j = 0; j < 8; ++j)
                    acc[i][j] = fmaf(av[i], bv[j], acc[i][j]);
        }
        if (kt < 63) {
            float* An = As[cur ^ 1]; float* Bn = Bs[cur ^ 1];
            An[(aq0 + 0) * 132 + ar0] = pa0.x; An[(aq0 + 1) * 132 + ar0] = pa0.y;
            An[(aq0 + 2) * 132 + ar0] = pa0.z; An[(aq0 + 3) * 132 + ar0] = pa0.w;
            An[(aq1 + 0) * 132 + ar1] = pa1.x; An[(aq1 + 1) * 132 + ar1] = pa1.y;
            An[(aq1 + 2) * 132 + ar1] = pa1.z; An[(aq1 + 3) * 132 + ar1] = pa1.w;
            Bn[(aq0 + 0) * 132 + ar0] = pb0.x; Bn[(aq0 + 1) * 132 + ar0] = pb0.y;
            Bn[(aq0 + 2) * 132 + ar0] = pb0.z; Bn[(aq0 + 3) * 132 + ar0] = pb0.w;
            Bn[(aq1 + 0) * 132 + ar1] = pb1.x; Bn[(aq1 + 1) * 132 + ar1] = pb1.y;
            Bn[(aq1 + 2) * 132 + ar1] = pb1.z; Bn[(aq1 + 3) * 132 + ar1] = pb1.w;
            __syncthreads();
        }
    }

    float* C = g_pre + (size_t)g * MROWS * DM + (size_t)blk * IB + (size_t)(ntile * 128) + ob;
#pragma unroll
    for (int i = 0; i < 8; ++i) {
        const size_t row = (size_t)(mtile * 128 + rb + i);
        *(float4*)(C + row * DM)     = make_float4(acc[i][0], acc[i][1], acc[i][2], acc[i][3]);
        *(float4*)(C + row * DM + 4) = make_float4(acc[i][4], acc[i][5], acc[i][6], acc[i][7]);
    }
}

// ---------------- kernel: 3xTF32 MMA GEMM (gates o,z — numerator-only) -----
// grid: x=mtile(64), y=ntile(8), z=blk*2+(g-2) (8). Reads silu'd g_xa.
__global__ __launch_bounds__(256, 2) void k_gemm_oz(const float* __restrict__ Wg) {
    __shared__ __align__(16) float As_hi[128 * 20];
    __shared__ __align__(16) float As_lo[128 * 20];
    __shared__ __align__(16) float Bs_hi[128 * 20];
    __shared__ __align__(16) float Bs_lo[128 * 20];

    const int mtile = blockIdx.x;
    const int ntile = blockIdx.y;
    const int g     = 2 + (blockIdx.z & 1);  // gate 2 or 3
    const int blk   = blockIdx.z >> 1;

    const int tid  = threadIdx.x;
    const int lane = tid & 31;
    const int wid  = tid >> 5;
    const int gid  = lane >> 2;
    const int tig  = lane & 3;
    const int warp_m = wid >> 2;
    const int warp_n = wid & 3;

    const float* Aptr = g_xa + (size_t)(mtile * 128) * DM + blk * IB;
    const float* Bptr = Wg + ((size_t)(g * 4 + blk)) * IB * IB + (size_t)(ntile * 128) * IB;

    float4 acc[4][4];
#pragma unroll
    for (int mi = 0; mi < 4; ++mi)
#pragma unroll
        for (int ni = 0; ni < 4; ++ni) acc[mi][ni] = make_float4(0.f, 0.f, 0.f, 0.f);

    const int q0 = tid, q1 = tid + 256;
    const int r0 = q0 >> 2, c0 = (q0 & 3) * 4;
    const int r1 = q1 >> 2, c1 = (q1 & 3) * 4;

#pragma unroll 1
    for (int kt = 0; kt < 64; ++kt) {
        const int k0 = kt * 16;
        float4 av0 = *(const float4*)(Aptr + (size_t)r0 * DM + k0 + c0);
        float4 av1 = *(const float4*)(Aptr + (size_t)r1 * DM + k0 + c1);
        float4 bv0 = *(const float4*)(Bptr + (size_t)r0 * IB + k0 + c0);
        float4 bv1 = *(const float4*)(Bptr + (size_t)r1 * IB + k0 + c1);

        __syncthreads();
        {
            float4 H, L;
            H.x = to_tf32(av0.x); L.x = to_tf32(av0.x - H.x);
            H.y = to_tf32(av0.y); L.y = to_tf32(av0.y - H.y);
            H.z = to_tf32(av0.z); L.z = to_tf32(av0.z - H.z);
            H.w = to_tf32(av0.w); L.w = to_tf32(av0.w - H.w);
            *(float4*)(As_hi + r0 * 20 + c0) = H;
            *(float4*)(As_lo + r0 * 20 + c0) = L;
            H.x = to_tf32(av1.x); L.x = to_tf32(av1.x - H.x);
            H.y = to_tf32(av1.y); L.y = to_tf32(av1.y - H.y);
            H.z = to_tf32(av1.z); L.z = to_tf32(av1.z - H.z);
            H.w = to_tf32(av1.w); L.w = to_tf32(av1.w - H.w);
            *(float4*)(As_hi + r1 * 20 + c1) = H;
            *(float4*)(As_lo + r1 * 20 + c1) = L;
            H.x = to_tf32(bv0.x); L.x = to_tf32(bv0.x - H.x);
            H.y = to_tf32(bv0.y); L.y = to_tf32(bv0.y - H.y);
            H.z = to_tf32(bv0.z); L.z = to_tf32(bv0.z - H.z);
            H.w = to_tf32(bv0.w); L.w = to_tf32(bv0.w - H.w);
            *(float4*)(Bs_hi + r0 * 20 + c0) = H;
            *(float4*)(Bs_lo + r0 * 20 + c0) = L;
            H.x = to_tf32(bv1.x); L.x = to_tf32(bv1.x - H.x);
            H.y = to_tf32(bv1.y); L.y = to_tf32(bv1.y - H.y);
            H.z = to_tf32(bv1.z); L.z = to_tf32(bv1.z - H.z);
            H.w = to_tf32(bv1.w); L.w = to_tf32(bv1.w - H.w);
            *(float4*)(Bs_hi + r1 * 20 + c1) = H;
            *(float4*)(Bs_lo + r1 * 20 + c1) = L;
        }
        __syncthreads();

#pragma unroll
        for (int ks = 0; ks < 16; ks += 8) {
            float ah[4][4], al[4][4];
#pragma unroll
            for (int mi = 0; mi < 4; ++mi) {
                const int ar = warp_m * 64 + mi * 16 + gid;
                ah[mi][0] = As_hi[ar * 20 + ks + tig];
                ah[mi][1] = As_hi[(ar + 8) * 20 + ks + tig];
                ah[mi][2] = As_hi[ar * 20 + ks + tig + 4];
                ah[mi][3] = As_hi[(ar + 8) * 20 + ks + tig + 4];
                al[mi][0] = As_lo[ar * 20 + ks + tig];
                al[mi][1] = As_lo[(ar + 8) * 20 + ks + tig];
                al[mi][2] = As_lo[ar * 20 + ks + tig + 4];
                al[mi][3] = As_lo[(ar + 8) * 20 + ks + tig + 4];
            }
#pragma unroll
            for (int ni = 0; ni < 4; ++ni) {
                const int br = warp_n * 32 + ni * 8 + gid;
                const float bh0 = Bs_hi[br * 20 + ks + tig];
                const float bh1 = Bs_hi[br * 20 + ks + tig + 4];
                const float bl0 = Bs_lo[br * 20 + ks + tig];
                const float bl1 = Bs_lo[br * 20 + ks + tig + 4];
#pragma unroll
                for (int mi = 0; mi < 4; ++mi) {
                    mma_tf32(acc[mi][ni], al[mi], bh0, bh1);
                    mma_tf32(acc[mi][ni], ah[mi], bl0, bl1);
                    mma_tf32(acc[mi][ni], ah[mi], bh0, bh1);
                }
            }
        }
    }

    float* C = g_pre + (size_t)g * MROWS * DM + (size_t)blk * IB;
#pragma unroll
    for (int mi = 0; mi < 4; ++mi) {
#pragma unroll
        for (int ni = 0; ni < 4; ++ni) {
            const int row = mtile * 128 + warp_m * 64 + mi * 16 + gid;
            const int col = ntile * 128 + warp_n * 32 + ni * 8 + tig * 2;
            *(float2*)(C + (size_t)row * DM + col) = make_float2(acc[mi][ni].x, acc[mi][ni].y);
            *(float2*)(C + (size_t)(row + 8) * DM + col) = make_float2(acc[mi][ni].z, acc[mi][ni].w);
        }
    }
}

// ---------------- kernel: row-wise gates (stats fp64, values fp32) ----------
__global__ __launch_bounds__(512) void k_pass2(const float* __restrict__ b_gates,
                                               const float* __restrict__ lng,
                                               const float* __restrict__ lnb) {
    __shared__ double s_red[16 * 8];
    const int tid = threadIdx.x;
    const int d0 = tid * 8;

    for (int row = blockIdx.x; row < MROWS; row += gridDim.x) {
        float p[4][8];
#pragma unroll
        for (int gg = 0; gg < 4; ++gg) {
            const float* base = g_pre + ((size_t)gg * MROWS + row) * DM + d0;
            float4 u = *(const float4*)(base);
            float4 v = *(const float4*)(base + 4);
            const float* bg = b_gates + gg * DM + d0;
            float4 w = *(const float4*)(bg);
            float4 y = *(const float4*)(bg + 4);
            p[gg][0] = __fadd_rn(u.x, w.x); p[gg][1] = __fadd_rn(u.y, w.y);
            p[gg][2] = __fadd_rn(u.z, w.z); p[gg][3] = __fadd_rn(u.w, w.w);
            p[gg][4] = __fadd_rn(v.x, y.x); p[gg][5] = __fadd_rn(v.y, y.y);
            p[gg][6] = __fadd_rn(v.z, y.z); p[gg][7] = __fadd_rn(v.w, y.w);
        }
        double v8[8];
#pragma unroll
        for (int gg = 0; gg < 4; ++gg) {
            double s = 0.0, q = 0.0;
#pragma unroll
            for (int c = 0; c < 8; ++c) {
                double pv = (double)p[gg][c];
                s += pv; q += pv * pv;
            }
            v8[2 * gg] = s; v8[2 * gg + 1] = q;
        }
        block_reduce_d<8>(v8, s_red);
        double mu[4], rs[4];
#pragma unroll
        for (int gg = 0; gg < 4; ++gg) {
            mu[gg] = v8[2 * gg] * (1.0 / DM);
            double var = v8[2 * gg + 1] * (1.0 / DM) - mu[gg] * mu[gg];
            rs[gg] = 1.0 / sqrt(var + EPSD);
        }
        float iv[8], cv[8], ov[8];
#pragma unroll
        for (int c = 0; c < 8; ++c) {
            const int d = d0 + c;
            float li = (float)((((double)p[0][c] - mu[0]) * rs[0]) * (double)lng[d]          + (double)lnb[d]);
            float lf = (float)((((double)p[1][c] - mu[1]) * rs[1]) * (double)lng[DM + d]     + (double)lnb[DM + d]);
            float lo = (float)((((double)p[2][c] - mu[2]) * rs[2]) * (double)lng[2 * DM + d] + (double)lnb[2 * DM + d]);
            float lz = (float)((((double)p[3][c] - mu[3]) * rs[3]) * (double)lng[3 * DM + d] + (double)lnb[3 * DM + d]);
            float m  = fmaxf(li, lf);
            float q  = __fadd_rn(li, -m);
            float ii = (float)exp((double)q);        // near-correctly-rounded f32 exp
            float zz = tanh_xla(lz);
            ov[c] = logistic_xla(lo);
            iv[c] = ii;
            cv[c] = __fmul_rn(ii, zz);
        }
        {
            float* ob = g_obuf + (size_t)row * DM + d0;
            *(float4*)(ob)     = make_float4(ov[0], ov[1], ov[2], ov[3]);
            *(float4*)(ob + 4) = make_float4(ov[4], ov[5], ov[6], ov[7]);
        }
        double v4[4] = {0.0, 0.0, 0.0, 0.0};
#pragma unroll
        for (int c = 0; c < 8; ++c) {
            double cd = (double)cv[c], id = (double)iv[c];
            v4[0] += cd; v4[1] += cd * cd;
            v4[2] += id; v4[3] += id * id;
        }
        block_reduce_d<4>(v4, s_red);
        const double muc = v4[0] * (1.0 / DM);
        const double rsc = 1.0 / sqrt(v4[1] * (1.0 / DM) - muc * muc + EPSD);
        const double mui = v4[2] * (1.0 / DM);
        const double rsi = 1.0 / sqrt(v4[3] * (1.0 / DM) - mui * mui + EPSD);
        float lc[8], ln_[8];
#pragma unroll
        for (int c = 0; c < 8; ++c) {
            const int d = d0 + c;
            lc[c]  = (float)((((double)cv[c] - muc) * rsc) * (double)lng[4 * DM + d] + (double)lnb[4 * DM + d]);
            ln_[c] = (float)((((double)iv[c] - mui) * rsi) * (double)lng[5 * DM + d] + (double)lnb[5 * DM + d]);
        }
        float* pc = g_lnct + (size_t)row * DM + d0;
        float* pn = g_lni + (size_t)row * DM + d0;
        *(float4*)(pc)     = make_float4(lc[0], lc[1], lc[2], lc[3]);
        *(float4*)(pc + 4) = make_float4(lc[4], lc[5], lc[6], lc[7]);
        *(float4*)(pn)     = make_float4(ln_[0], ln_[1], ln_[2], ln_[3]);
        *(float4*)(pn + 4) = make_float4(ln_[4], ln_[5], ln_[6], ln_[7]);
    }
}

// ---------------- kernel: SEQUENTIAL ascending-row fp32 column sums ---------
__global__ __launch_bounds__(32) void k_redsum() {
    const int d = blockIdx.x * 32 + threadIdx.x;
    const float* pc = g_lnct + d;
    const float* pn = g_lni + d;
    float ac = 0.0f, an = 0.0f;
#pragma unroll 16
    for (int row = 0; row < MROWS; ++row) {
        ac = __fadd_rn(ac, __ldg(pc + (size_t)row * DM));
        an = __fadd_rn(an, __ldg(pn + (size_t)row * DM));
    }
    const float cm = __fmul_rn(ac, 1.0f / MROWS);
    const float nm = __fmul_rn(an, 1.0f / MROWS);
    g_ratio[d] = __fdiv_rn(cm, nm);
}

// ---------------- kernel: ht pass (non-amplified; fp64 stats) ----------------
__global__ __launch_bounds__(512) void k_pass3(const float* __restrict__ lng,
                                               const float* __restrict__ lnb) {
    __shared__ double s_htm[DM];
    __shared__ double s_red[16 * 2];
    const int tid = threadIdx.x;
    for (int d = tid; d < DM; d += 512) s_htm[d] = 0.0;
    __syncthreads();
    const int d0 = tid * 8;
    float rr[8];
#pragma unroll
    for (int c = 0; c < 8; ++c) rr[c] = g_ratio[d0 + c];

    for (int row = blockIdx.x; row < MROWS; row += gridDim.x) {
        const float* ob = g_obuf + (size_t)row * DM + d0;
        float4 u = *(const float4*)(ob);
        float4 v = *(const float4*)(ob + 4);
        float h[8] = {__fmul_rn(u.x, rr[0]), __fmul_rn(u.y, rr[1]),
                      __fmul_rn(u.z, rr[2]), __fmul_rn(u.w, rr[3]),
                      __fmul_rn(v.x, rr[4]), __fmul_rn(v.y, rr[5]),
                      __fmul_rn(v.z, rr[6]), __fmul_rn(v.w, rr[7])};
        double v2[2] = {0.0, 0.0};
#pragma unroll
        for (int c = 0; c < 8; ++c) { double hd = (double)h[c]; v2[0] += hd; v2[1] += hd * hd; }
        block_reduce_d<2>(v2, s_red);
        const double mu = v2[0] * (1.0 / DM);
        const double rs = 1.0 / sqrt(v2[1] * (1.0 / DM) - mu * mu + EPSD);
#pragma unroll
        for (int c = 0; c < 8; ++c) {
            const int d = d0 + c;
            s_htm[d] += ((double)h[c] - mu) * rs * (double)lng[6 * DM + d] + (double)lnb[6 * DM + d];
        }
    }
    __syncthreads();
    for (int d = tid; d < DM; d += 512) atomicAdd(&g_htmsum[d], s_htm[d]);
}

// ---------------- kernel: slstm_out = LN(mean ht) (fp64) ----------------
__global__ __launch_bounds__(512) void k_pass4(const float* __restrict__ lng,
                                               const float* __restrict__ lnb) {
    __shared__ double s_red[16 * 2];
    const int tid = threadIdx.x;
    const int d0 = tid * 8;
    double h[8];
#pragma unroll
    for (int c = 0; c < 8; ++c) h[c] = g_htmsum[d0 + c] * (1.0 / MROWS);
    double v2[2] = {0.0, 0.0};
#pragma unroll
    for (int c = 0; c < 8; ++c) { v2[0] += h[c]; v2[1] += h[c] * h[c]; }
    block_reduce_d<2>(v2, s_red);
    const double mu = v2[0] * (1.0 / DM);
    const double rs = 1.0 / sqrt(v2[1] * (1.0 / DM) - mu * mu + EPSD);
#pragma unroll
    for (int c = 0; c < 8; ++c) {
        const int d = d0 + c;
        g_s[d] = (h[c] - mu) * rs * (double)lng[7 * DM + d] + (double)lnb[7 * DM + d];
    }
}

// ---------------- kernel: left/right GEMVs + gelu + product (fp64) ----------
__global__ __launch_bounds__(128) void k_pass5(const float* __restrict__ Wl,
                                               const float* __restrict__ bl,
                                               const float* __restrict__ Wr,
                                               const float* __restrict__ br) {
    __shared__ double s_red[4 * 2];
    const int j = blockIdx.x;
    const int tid = threadIdx.x;
    double v2[2] = {0.0, 0.0};
    const float* wl = Wl + (size_t)j * DM;
    const float* wr = Wr + (size_t)j * DM;
    for (int d = tid; d < DM; d += 128) {
        const double s = g_s[d];
        v2[0] += s * (double)wl[d];
        v2[1] += s * (double)wr[d];
    }
    block_reduce_d<2>(v2, s_red);
    if (tid == 0) {
        const double left = v2[0] + (double)bl[j];
        double right = v2[1] + (double)br[j];
        right = 0.5 * right * (1.0 + erf(right * 0.7071067811865475244));  // exact gelu
        g_v[j] = left * right;
    }
}

// ---------------- kernel: LN over DFF (fp64) ----------------
__global__ __launch_bounds__(512) void k_pass6a(const float* __restrict__ og,
                                                const float* __restrict__ ob) {
    __shared__ double s_red[16 * 2];
    const int tid = threadIdx.x;
    double v2[2] = {0.0, 0.0};
    for (int jj = tid; jj < DFF; jj += 512) {
        const double x = g_v[jj];
        v2[0] += x; v2[1] += x * x;
    }
    block_reduce_d<2>(v2, s_red);
    const double mu = v2[0] * (1.0 / DFF);
    const double rs = 1.0 / sqrt(v2[1] * (1.0 / DFF) - mu * mu + EPSD);
    for (int jj = tid; jj < DFF; jj += 512)
        g_u[jj] = (g_v[jj] - mu) * rs * (double)og[jj] + (double)ob[jj];
}

// ---------------- kernel: final projection GEMV (fp64) ----------------
__global__ __launch_bounds__(128) void k_pass6b(const float* __restrict__ Wp,
                                                const float* __restrict__ bp,
                                                float* __restrict__ out) {
    __shared__ double s_red[4 * 1];
    const int d = blockIdx.x;
    const int tid = threadIdx.x;
    double acc[1] = {0.0};
    const float* wp = Wp + (size_t)d * DFF;
    for (int jj = tid; jj < DFF; jj += 128) acc[0] += g_u[jj] * (double)wp[jj];
    block_reduce_d<1>(acc, s_red);
    if (tid == 0) out[d] = (float)(acc[0] + (double)bp[d]);
}

// ---------------- launcher ----------------
extern "C" void kernel_launch(void* const* d_in, const int* in_sizes, int n_in,
                              void* d_out, int out_size) {
    const float* x      = (const float*)d_in[0];
    const float* Wg     = (const float*)d_in[1];
    const float* bgates = (const float*)d_in[2];
    // d_in[3] = Wr_gates: multiplies zero initial state -> unused
    const float* lng    = (const float*)d_in[4];
    const float* lnb    = (const float*)d_in[5];
    const float* lnoutg = (const float*)d_in[6];
    const float* lnoutb = (const float*)d_in[7];
    const float* Wl     = (const float*)d_in[8];
    const float* bl     = (const float*)d_in[9];
    const float* Wr     = (const float*)d_in[10];
    const float* br     = (const float*)d_in[11];
    const float* Wp     = (const float*)d_in[12];
    const float* bp     = (const float*)d_in[13];
    float* out = (float*)d_out;

    k_zero<<<8, 512>>>();
    k_silu<<<(MROWS * (size_t)DM) / (256 * 4), 256>>>(x);
    k_gemm_oz<<<dim3(64, 8, 8), 256>>>(Wg);   // gates o,z via TF32 tensor cores
    k_gemm_if<<<dim3(64, 8, 8), 256>>>(Wg);   // gates i,f bit-exact scalar
    k_pass2<<<296, 512>>>(bgates, lng, lnb);
    k_redsum<<<DM / 32, 32>>>();
    k_pass3<<<296, 512>>>(lng, lnb);
    k_pass4<<<1, 512>>>(lng, lnb);
    k_pass5<<<DFF, 128>>>(Wl, bl, Wr, br);
    k_pass6a<<<1, 512>>>(lnoutg, lnoutb);
    k_pass6b<<<DM, 128>>>(Wp, bp, out);
}

// round 8
// speedup vs baseline: 1.8923x; 1.1300x over previous
#include <cuda_runtime.h>
#include <math.h>
#include <stdint.h>

// ---------------- problem constants ----------------
#define DM      4096
#define MROWS   8192          // B*N = 4*2048
#define IB      1024          // block size (DM / 4 blocks)
#define DFF     5461
#define EPSD    1e-5

// ---------------- scratch (device globals; no allocations allowed) ----------
__device__ float  g_xa[(size_t)MROWS * DM];        // 128 MB silu(x)
__device__ float  g_pre[4ULL * MROWS * DM];        // 512 MB gate pre-activations
__device__ float  g_lnct[(size_t)MROWS * DM];      // 128 MB LN(i*z) values
__device__ float  g_lni[(size_t)MROWS * DM];       // 128 MB LN(i) values
__device__ float  g_obuf[(size_t)MROWS * DM];      // 128 MB o-gate values
__device__ float  g_ratio[DM];                     // ct/nt (fp32, ref-matched)
__device__ double g_htmsum[DM];
__device__ double g_s[DM];                         // slstm_out
__device__ double g_v[DFF];                        // left*right (pre-LN)
__device__ double g_u[DFF];                        // LN'd

// ---------------- XLA-matched elementwise math ----------------
__device__ __forceinline__ float tanh_xla(float x) {
    const float kMax = 7.90531110763549805f;
    float cx = fminf(fmaxf(x, -kMax), kMax);
    float x2 = __fmul_rn(cx, cx);
    float p = fmaf(x2, -2.76076847742355e-16f, 2.00018790482477e-13f);
    p = fmaf(p, x2, -8.60467152213735e-11f);
    p = fmaf(p, x2, 5.12229709037114e-08f);
    p = fmaf(p, x2, 1.48572235717979e-05f);
    p = fmaf(p, x2, 6.37261928875436e-04f);
    p = fmaf(p, x2, 4.89352455891786e-03f);
    p = __fmul_rn(cx, p);
    float q = fmaf(x2, 1.19825839466702e-06f, 1.18534705686654e-04f);
    q = fmaf(q, x2, 2.26843463243900e-03f);
    q = fmaf(q, x2, 4.89352518554385e-03f);
    float r = __fdiv_rn(p, q);
    return (fabsf(x) < 0.0004f) ? x : r;
}

__device__ __forceinline__ float logistic_xla(float x) {
    return fmaf(0.5f, tanh_xla(__fmul_rn(0.5f, x)), 0.5f);
}

__device__ __forceinline__ float silu_xla(float x) {
    return __fmul_rn(x, logistic_xla(x));
}

// ---------------- TF32 helpers ----------------
__device__ __forceinline__ float to_tf32(float v) {
    unsigned u;
    asm("cvt.rna.tf32.f32 %0, %1;" : "=r"(u) : "f"(v));
    return __uint_as_float(u);
}

__device__ __forceinline__ void mma_tf32(float4& d, const float* a, float b0, float b1) {
    asm volatile(
        "mma.sync.aligned.m16n8k8.row.col.f32.tf32.tf32.f32 "
        "{%0,%1,%2,%3}, {%4,%5,%6,%7}, {%8,%9}, {%0,%1,%2,%3};\n"
        : "+f"(d.x), "+f"(d.y), "+f"(d.z), "+f"(d.w)
        : "r"(__float_as_uint(a[0])), "r"(__float_as_uint(a[1])),
          "r"(__float_as_uint(a[2])), "r"(__float_as_uint(a[3])),
          "r"(__float_as_uint(b0)), "r"(__float_as_uint(b1)));
}

// ---------------- fp64 block reduce ----------------
template <int NV>
__device__ __forceinline__ void block_reduce_d(double* v, double* sred) {
    const int lane = threadIdx.x & 31;
    const int wid  = threadIdx.x >> 5;
    const int nw   = (blockDim.x + 31) >> 5;
#pragma unroll
    for (int i = 0; i < NV; ++i) {
        double x = v[i];
#pragma unroll
        for (int o = 16; o > 0; o >>= 1) x += __shfl_xor_sync(0xffffffffu, x, o);
        v[i] = x;
    }
    __syncthreads();
    if (lane == 0) {
#pragma unroll
        for (int i = 0; i < NV; ++i) sred[wid * NV + i] = v[i];
    }
    __syncthreads();
    if (wid == 0) {
#pragma unroll
        for (int i = 0; i < NV; ++i) {
            double x = (lane < nw) ? sred[lane * NV + i] : 0.0;
#pragma unroll
            for (int o = 16; o > 0; o >>= 1) x += __shfl_xor_sync(0xffffffffu, x, o);
            if (lane == 0) sred[i] = x;
        }
    }
    __syncthreads();
#pragma unroll
    for (int i = 0; i < NV; ++i) v[i] = sred[i];
    __syncthreads();
}

// ---------------- kernel: zero + silu ----------------
__global__ void k_zero() {
    int idx = blockIdx.x * blockDim.x + threadIdx.x;
    if (idx < DM) g_htmsum[idx] = 0.0;
}

__global__ __launch_bounds__(256) void k_silu(const float* __restrict__ x) {
    size_t i = ((size_t)blockIdx.x * 256 + threadIdx.x) * 4;
    float4 v = *(const float4*)(x + i);
    v.x = silu_xla(v.x); v.y = silu_xla(v.y); v.z = silu_xla(v.z); v.w = silu_xla(v.w);
    *(float4*)(g_xa + i) = v;
}

// ---------------- kernel: scalar fp32 SGEMM (gates i,f), ascending-k -------
// Bit-exact match of XLA's sgemm chains; only gates 0,1 feed the amplified
// denominator path. grid: x=mtile(64), y=ntile(8), z=blk*2+g (8), g in {0,1}.
// Column mapping per thread: {4tx..4tx+3} and {64+4tx..} (2-way banks max).
__global__ __launch_bounds__(256, 2) void k_gemm_if(const float* __restrict__ Wg) {
    __shared__ __align__(16) float As[2][16 * 132];
    __shared__ __align__(16) float Bs[2][16 * 132];

    const int mtile = blockIdx.x;
    const int ntile = blockIdx.y;
    const int g     = blockIdx.z & 1;        // gate 0 or 1
    const int blk   = blockIdx.z >> 1;

    const int tid = threadIdx.x;
    const int tx  = tid & 15;
    const int ty  = tid >> 4;
    const int rb  = ty * 8;
    const int nb1 = tx * 4;
    const int nb2 = 64 + tx * 4;

    const float* aBase = g_xa + (size_t)(mtile * 128) * DM + blk * IB;
    const float* bBase = Wg + ((size_t)(g * 4 + blk)) * IB * IB + (size_t)(ntile * 128) * IB;

    const int s0 = tid, s1 = tid + 256;
    const int ar0 = s0 >> 2, aq0 = (s0 & 3) * 4;
    const int ar1 = s1 >> 2, aq1 = (s1 & 3) * 4;

    float acc[8][8];
#pragma unroll
    for (int i = 0; i < 8; ++i)
#pragma unroll
        for (int j = 0; j < 8; ++j) acc[i][j] = 0.0f;

    float4 pa0, pa1, pb0, pb1;
    pa0 = *(const float4*)(aBase + (size_t)ar0 * DM + aq0);
    pa1 = *(const float4*)(aBase + (size_t)ar1 * DM + aq1);
    pb0 = *(const float4*)(bBase + (size_t)ar0 * IB + aq0);
    pb1 = *(const float4*)(bBase + (size_t)ar1 * IB + aq1);
    {
        float* A = As[0]; float* B = Bs[0];
        A[(aq0 + 0) * 132 + ar0] = pa0.x; A[(aq0 + 1) * 132 + ar0] = pa0.y;
        A[(aq0 + 2) * 132 + ar0] = pa0.z; A[(aq0 + 3) * 132 + ar0] = pa0.w;
        A[(aq1 + 0) * 132 + ar1] = pa1.x; A[(aq1 + 1) * 132 + ar1] = pa1.y;
        A[(aq1 + 2) * 132 + ar1] = pa1.z; A[(aq1 + 3) * 132 + ar1] = pa1.w;
        B[(aq0 + 0) * 132 + ar0] = pb0.x; B[(aq0 + 1) * 132 + ar0] = pb0.y;
        B[(aq0 + 2) * 132 + ar0] = pb0.z; B[(aq0 + 3) * 132 + ar0] = pb0.w;
        B[(aq1 + 0) * 132 + ar1] = pb1.x; B[(aq1 + 1) * 132 + ar1] = pb1.y;
        B[(aq1 + 2) * 132 + ar1] = pb1.z; B[(aq1 + 3) * 132 + ar1] = pb1.w;
    }
    __syncthreads();

#pragma unroll 1
    for (int kt = 0; kt < 64; ++kt) {
        const int cur = kt & 1;
        if (kt < 63) {
            const int k0 = (kt + 1) * 16;
            pa0 = *(const float4*)(aBase + (size_t)ar0 * DM + k0 + aq0);
            pa1 = *(const float4*)(aBase + (size_t)ar1 * DM + k0 + aq1);
            pb0 = *(const float4*)(bBase + (size_t)ar0 * IB + k0 + aq0);
            pb1 = *(const float4*)(bBase + (size_t)ar1 * IB + k0 + aq1);
        }
        const float* A = As[cur];
        const float* B = Bs[cur];
#pragma unroll
        for (int k = 0; k < 16; ++k) {
            float4 a0 = *(const float4*)(A + k * 132 + rb);
            float4 a1 = *(const float4*)(A + k * 132 + rb + 4);
            float4 b0 = *(const float4*)(B + k * 132 + nb1);
            float4 b1 = *(const float4*)(B + k * 132 + nb2);
            float av[8] = {a0.x, a0.y, a0.z, a0.w, a1.x, a1.y, a1.z, a1.w};
            float bv[8] = {b0.x, b0.y, b0.z, b0.w, b1.x, b1.y, b1.z, b1.w};
#pragma unroll
            for (int i = 0; i < 8; ++i)
#pragma unroll
                for (int j = 0; j < 8; ++j)
                    acc[i][j] = fmaf(av[i], bv[j], acc[i][j]);
        }
        if (kt < 63) {
            float* An = As[cur ^ 1]; float* Bn = Bs[cur ^ 1];
            An[(aq0 + 0) * 132 + ar0] = pa0.x; An[(aq0 + 1) * 132 + ar0] = pa0.y;
            An[(aq0 + 2) * 132 + ar0] = pa0.z; An[(aq0 + 3) * 132 + ar0] = pa0.w;
            An[(aq1 + 0) * 132 + ar1] = pa1.x; An[(aq1 + 1) * 132 + ar1] = pa1.y;
            An[(aq1 + 2) * 132 + ar1] = pa1.z; An[(aq1 + 3) * 132 + ar1] = pa1.w;
            Bn[(aq0 + 0) * 132 + ar0] = pb0.x; Bn[(aq0 + 1) * 132 + ar0] = pb0.y;
            Bn[(aq0 + 2) * 132 + ar0] = pb0.z; Bn[(aq0 + 3) * 132 + ar0] = pb0.w;
            Bn[(aq1 + 0) * 132 + ar1] = pb1.x; Bn[(aq1 + 1) * 132 + ar1] = pb1.y;
            Bn[(aq1 + 2) * 132 + ar1] = pb1.z; Bn[(aq1 + 3) * 132 + ar1] = pb1.w;
            __syncthreads();
        }
    }

    float* C = g_pre + (size_t)g * MROWS * DM + (size_t)blk * IB + (size_t)(ntile * 128);
#pragma unroll
    for (int i = 0; i < 8; ++i) {
        const size_t row = (size_t)(mtile * 128 + rb + i);
        *(float4*)(C + row * DM + nb1) = make_float4(acc[i][0], acc[i][1], acc[i][2], acc[i][3]);
        *(float4*)(C + row * DM + nb2) = make_float4(acc[i][4], acc[i][5], acc[i][6], acc[i][7]);
    }
}

// ---------------- kernel: single-term TF32 MMA GEMM (gates o,z) ------------
// Numerator-only gates tolerate tf32 (predicted final contribution ~1e-4).
// [k][*] smem layout, stride 136 (conflict-free fragment LDS), tf32 convert
// at smem store, register-prefetch double buffer, one sync per k-tile.
// grid: x=mtile(64), y=ntile(8), z=blk*2+(g-2) (8).
__global__ __launch_bounds__(256, 2) void k_gemm_oz(const float* __restrict__ Wg) {
    __shared__ __align__(16) float As[2][16 * 136];
    __shared__ __align__(16) float Bs[2][16 * 136];

    const int mtile = blockIdx.x;
    const int ntile = blockIdx.y;
    const int g     = 2 + (blockIdx.z & 1);  // gate 2 or 3
    const int blk   = blockIdx.z >> 1;

    const int tid  = threadIdx.x;
    const int lane = tid & 31;
    const int wid  = tid >> 5;
    const int gid  = lane >> 2;
    const int tig  = lane & 3;
    const int warp_m = wid >> 2;             // 0..1
    const int warp_n = wid & 3;              // 0..3

    const float* aBase = g_xa + (size_t)(mtile * 128) * DM + blk * IB;
    const float* bBase = Wg + ((size_t)(g * 4 + blk)) * IB * IB + (size_t)(ntile * 128) * IB;

    const int s0 = tid, s1 = tid + 256;
    const int ar0 = s0 >> 2, aq0 = (s0 & 3) * 4;
    const int ar1 = s1 >> 2, aq1 = (s1 & 3) * 4;

    float4 acc[4][4];
#pragma unroll
    for (int mi = 0; mi < 4; ++mi)
#pragma unroll
        for (int ni = 0; ni < 4; ++ni) acc[mi][ni] = make_float4(0.f, 0.f, 0.f, 0.f);

    float4 pa0, pa1, pb0, pb1;
    pa0 = *(const float4*)(aBase + (size_t)ar0 * DM + aq0);
    pa1 = *(const float4*)(aBase + (size_t)ar1 * DM + aq1);
    pb0 = *(const float4*)(bBase + (size_t)ar0 * IB + aq0);
    pb1 = *(const float4*)(bBase + (size_t)ar1 * IB + aq1);
    {
        float* A = As[0]; float* B = Bs[0];
        A[(aq0 + 0) * 136 + ar0] = to_tf32(pa0.x); A[(aq0 + 1) * 136 + ar0] = to_tf32(pa0.y);
        A[(aq0 + 2) * 136 + ar0] = to_tf32(pa0.z); A[(aq0 + 3) * 136 + ar0] = to_tf32(pa0.w);
        A[(aq1 + 0) * 136 + ar1] = to_tf32(pa1.x); A[(aq1 + 1) * 136 + ar1] = to_tf32(pa1.y);
        A[(aq1 + 2) * 136 + ar1] = to_tf32(pa1.z); A[(aq1 + 3) * 136 + ar1] = to_tf32(pa1.w);
        B[(aq0 + 0) * 136 + ar0] = to_tf32(pb0.x); B[(aq0 + 1) * 136 + ar0] = to_tf32(pb0.y);
        B[(aq0 + 2) * 136 + ar0] = to_tf32(pb0.z); B[(aq0 + 3) * 136 + ar0] = to_tf32(pb0.w);
        B[(aq1 + 0) * 136 + ar1] = to_tf32(pb1.x); B[(aq1 + 1) * 136 + ar1] = to_tf32(pb1.y);
        B[(aq1 + 2) * 136 + ar1] = to_tf32(pb1.z); B[(aq1 + 3) * 136 + ar1] = to_tf32(pb1.w);
    }
    __syncthreads();

#pragma unroll 1
    for (int kt = 0; kt < 64; ++kt) {
        const int cur = kt & 1;
        if (kt < 63) {
            const int k0 = (kt + 1) * 16;
            pa0 = *(const float4*)(aBase + (size_t)ar0 * DM + k0 + aq0);
            pa1 = *(const float4*)(aBase + (size_t)ar1 * DM + k0 + aq1);
            pb0 = *(const float4*)(bBase + (size_t)ar0 * IB + k0 + aq0);
            pb1 = *(const float4*)(bBase + (size_t)ar1 * IB + k0 + aq1);
        }
        const float* A = As[cur];
        const float* B = Bs[cur];
#pragma unroll
        for (int ks = 0; ks < 16; ks += 8) {
            float a_[4][4];
#pragma unroll
            for (int mi = 0; mi < 4; ++mi) {
                const int rm = warp_m * 64 + mi * 16 + gid;
                a_[mi][0] = A[(ks + tig) * 136 + rm];
                a_[mi][1] = A[(ks + tig) * 136 + rm + 8];
                a_[mi][2] = A[(ks + tig + 4) * 136 + rm];
                a_[mi][3] = A[(ks + tig + 4) * 136 + rm + 8];
            }
#pragma unroll
            for (int ni = 0; ni < 4; ++ni) {
                const int nb = warp_n * 32 + ni * 8 + gid;
                const float b0 = B[(ks + tig) * 136 + nb];
                const float b1 = B[(ks + tig + 4) * 136 + nb];
#pragma unroll
                for (int mi = 0; mi < 4; ++mi)
                    mma_tf32(acc[mi][ni], a_[mi], b0, b1);
            }
        }
        if (kt < 63) {
            float* An = As[cur ^ 1]; float* Bn = Bs[cur ^ 1];
            An[(aq0 + 0) * 136 + ar0] = to_tf32(pa0.x); An[(aq0 + 1) * 136 + ar0] = to_tf32(pa0.y);
            An[(aq0 + 2) * 136 + ar0] = to_tf32(pa0.z); An[(aq0 + 3) * 136 + ar0] = to_tf32(pa0.w);
            An[(aq1 + 0) * 136 + ar1] = to_tf32(pa1.x); An[(aq1 + 1) * 136 + ar1] = to_tf32(pa1.y);
            An[(aq1 + 2) * 136 + ar1] = to_tf32(pa1.z); An[(aq1 + 3) * 136 + ar1] = to_tf32(pa1.w);
            Bn[(aq0 + 0) * 136 + ar0] = to_tf32(pb0.x); Bn[(aq0 + 1) * 136 + ar0] = to_tf32(pb0.y);
            Bn[(aq0 + 2) * 136 + ar0] = to_tf32(pb0.z); Bn[(aq0 + 3) * 136 + ar0] = to_tf32(pb0.w);
            Bn[(aq1 + 0) * 136 + ar1] = to_tf32(pb1.x); Bn[(aq1 + 1) * 136 + ar1] = to_tf32(pb1.y);
            Bn[(aq1 + 2) * 136 + ar1] = to_tf32(pb1.z); Bn[(aq1 + 3) * 136 + ar1] = to_tf32(pb1.w);
            __syncthreads();
        }
    }

    float* C = g_pre + (size_t)g * MROWS * DM + (size_t)blk * IB;
#pragma unroll
    for (int mi = 0; mi < 4; ++mi) {
#pragma unroll
        for (int ni = 0; ni < 4; ++ni) {
            const int row = mtile * 128 + warp_m * 64 + mi * 16 + gid;
            const int col = ntile * 128 + warp_n * 32 + ni * 8 + tig * 2;
            *(float2*)(C + (size_t)row * DM + col) = make_float2(acc[mi][ni].x, acc[mi][ni].y);
            *(float2*)(C + (size_t)(row + 8) * DM + col) = make_float2(acc[mi][ni].z, acc[mi][ni].w);
        }
    }
}

// ---------------- kernel: row-wise gates (stats fp64, values fp32) ----------
__global__ __launch_bounds__(512) void k_pass2(const float* __restrict__ b_gates,
                                               const float* __restrict__ lng,
                                               const float* __restrict__ lnb) {
    __shared__ double s_red[16 * 8];
    const int tid = threadIdx.x;
    const int d0 = tid * 8;

    for (int row = blockIdx.x; row < MROWS; row += gridDim.x) {
        float p[4][8];
#pragma unroll
        for (int gg = 0; gg < 4; ++gg) {
            const float* base = g_pre + ((size_t)gg * MROWS + row) * DM + d0;
            float4 u = *(const float4*)(base);
            float4 v = *(const float4*)(base + 4);
            const float* bg = b_gates + gg * DM + d0;
            float4 w = *(const float4*)(bg);
            float4 y = *(const float4*)(bg + 4);
            p[gg][0] = __fadd_rn(u.x, w.x); p[gg][1] = __fadd_rn(u.y, w.y);
            p[gg][2] = __fadd_rn(u.z, w.z); p[gg][3] = __fadd_rn(u.w, w.w);
            p[gg][4] = __fadd_rn(v.x, y.x); p[gg][5] = __fadd_rn(v.y, y.y);
            p[gg][6] = __fadd_rn(v.z, y.z); p[gg][7] = __fadd_rn(v.w, y.w);
        }
        double v8[8];
#pragma unroll
        for (int gg = 0; gg < 4; ++gg) {
            double s = 0.0, q = 0.0;
#pragma unroll
            for (int c = 0; c < 8; ++c) {
                double pv = (double)p[gg][c];
                s += pv; q += pv * pv;
            }
            v8[2 * gg] = s; v8[2 * gg + 1] = q;
        }
        block_reduce_d<8>(v8, s_red);
        double mu[4], rs[4];
#pragma unroll
        for (int gg = 0; gg < 4; ++gg) {
            mu[gg] = v8[2 * gg] * (1.0 / DM);
            double var = v8[2 * gg + 1] * (1.0 / DM) - mu[gg] * mu[gg];
            rs[gg] = 1.0 / sqrt(var + EPSD);
        }
        float iv[8], cv[8], ov[8];
#pragma unroll
        for (int c = 0; c < 8; ++c) {
            const int d = d0 + c;
            float li = (float)((((double)p[0][c] - mu[0]) * rs[0]) * (double)lng[d]          + (double)lnb[d]);
            float lf = (float)((((double)p[1][c] - mu[1]) * rs[1]) * (double)lng[DM + d]     + (double)lnb[DM + d]);
            float lo = (float)((((double)p[2][c] - mu[2]) * rs[2]) * (double)lng[2 * DM + d] + (double)lnb[2 * DM + d]);
            float lz = (float)((((double)p[3][c] - mu[3]) * rs[3]) * (double)lng[3 * DM + d] + (double)lnb[3 * DM + d]);
            float m  = fmaxf(li, lf);
            float q  = __fadd_rn(li, -m);
            float ii = (float)exp((double)q);        // near-correctly-rounded f32 exp
            float zz = tanh_xla(lz);
            ov[c] = logistic_xla(lo);
            iv[c] = ii;
            cv[c] = __fmul_rn(ii, zz);
        }
        {
            float* ob = g_obuf + (size_t)row * DM + d0;
            *(float4*)(ob)     = make_float4(ov[0], ov[1], ov[2], ov[3]);
            *(float4*)(ob + 4) = make_float4(ov[4], ov[5], ov[6], ov[7]);
        }
        double v4[4] = {0.0, 0.0, 0.0, 0.0};
#pragma unroll
        for (int c = 0; c < 8; ++c) {
            double cd = (double)cv[c], id = (double)iv[c];
            v4[0] += cd; v4[1] += cd * cd;
            v4[2] += id; v4[3] += id * id;
        }
        block_reduce_d<4>(v4, s_red);
        const double muc = v4[0] * (1.0 / DM);
        const double rsc = 1.0 / sqrt(v4[1] * (1.0 / DM) - muc * muc + EPSD);
        const double mui = v4[2] * (1.0 / DM);
        const double rsi = 1.0 / sqrt(v4[3] * (1.0 / DM) - mui * mui + EPSD);
        float lc[8], ln_[8];
#pragma unroll
        for (int c = 0; c < 8; ++c) {
            const int d = d0 + c;
            lc[c]  = (float)((((double)cv[c] - muc) * rsc) * (double)lng[4 * DM + d] + (double)lnb[4 * DM + d]);
            ln_[c] = (float)((((double)iv[c] - mui) * rsi) * (double)lng[5 * DM + d] + (double)lnb[5 * DM + d]);
        }
        float* pc = g_lnct + (size_t)row * DM + d0;
        float* pn = g_lni + (size_t)row * DM + d0;
        *(float4*)(pc)     = make_float4(lc[0], lc[1], lc[2], lc[3]);
        *(float4*)(pc + 4) = make_float4(lc[4], lc[5], lc[6], lc[7]);
        *(float4*)(pn)     = make_float4(ln_[0], ln_[1], ln_[2], ln_[3]);
        *(float4*)(pn + 4) = make_float4(ln_[4], ln_[5], ln_[6], ln_[7]);
    }
}

// ---------------- kernel: SEQUENTIAL ascending-row fp32 column sums ---------
__global__ __launch_bounds__(32) void k_redsum() {
    const int d = blockIdx.x * 32 + threadIdx.x;
    const float* pc = g_lnct + d;
    const float* pn = g_lni + d;
    float ac = 0.0f, an = 0.0f;
#pragma unroll 16
    for (int row = 0; row < MROWS; ++row) {
        ac = __fadd_rn(ac, __ldg(pc + (size_t)row * DM));
        an = __fadd_rn(an, __ldg(pn + (size_t)row * DM));
    }
    const float cm = __fmul_rn(ac, 1.0f / MROWS);
    const float nm = __fmul_rn(an, 1.0f / MROWS);
    g_ratio[d] = __fdiv_rn(cm, nm);
}

// ---------------- kernel: ht pass (non-amplified; fp64 stats) ----------------
__global__ __launch_bounds__(512) void k_pass3(const float* __restrict__ lng,
                                               const float* __restrict__ lnb) {
    __shared__ double s_htm[DM];
    __shared__ double s_red[16 * 2];
    const int tid = threadIdx.x;
    for (int d = tid; d < DM; d += 512) s_htm[d] = 0.0;
    __syncthreads();
    const int d0 = tid * 8;
    float rr[8];
#pragma unroll
    for (int c = 0; c < 8; ++c) rr[c] = g_ratio[d0 + c];

    for (int row = blockIdx.x; row < MROWS; row += gridDim.x) {
        const float* ob = g_obuf + (size_t)row * DM + d0;
        float4 u = *(const float4*)(ob);
        float4 v = *(const float4*)(ob + 4);
        float h[8] = {__fmul_rn(u.x, rr[0]), __fmul_rn(u.y, rr[1]),
                      __fmul_rn(u.z, rr[2]), __fmul_rn(u.w, rr[3]),
                      __fmul_rn(v.x, rr[4]), __fmul_rn(v.y, rr[5]),
                      __fmul_rn(v.z, rr[6]), __fmul_rn(v.w, rr[7])};
        double v2[2] = {0.0, 0.0};
#pragma unroll
        for (int c = 0; c < 8; ++c) { double hd = (double)h[c]; v2[0] += hd; v2[1] += hd * hd; }
        block_reduce_d<2>(v2, s_red);
        const double mu = v2[0] * (1.0 / DM);
        const double rs = 1.0 / sqrt(v2[1] * (1.0 / DM) - mu * mu + EPSD);
#pragma unroll
        for (int c = 0; c < 8; ++c) {
            const int d = d0 + c;
            s_htm[d] += ((double)h[c] - mu) * rs * (double)lng[6 * DM + d] + (double)lnb[6 * DM + d];
        }
    }
    __syncthreads();
    for (int d = tid; d < DM; d += 512) atomicAdd(&g_htmsum[d], s_htm[d]);
}

// ---------------- kernel: slstm_out = LN(mean ht) (fp64) ----------------
__global__ __launch_bounds__(512) void k_pass4(const float* __restrict__ lng,
                                               const float* __restrict__ lnb) {
    __shared__ double s_red[16 * 2];
    const int tid = threadIdx.x;
    const int d0 = tid * 8;
    double h[8];
#pragma unroll
    for (int c = 0; c < 8; ++c) h[c] = g_htmsum[d0 + c] * (1.0 / MROWS);
    double v2[2] = {0.0, 0.0};
#pragma unroll
    for (int c = 0; c < 8; ++c) { v2[0] += h[c]; v2[1] += h[c] * h[c]; }
    block_reduce_d<2>(v2, s_red);
    const double mu = v2[0] * (1.0 / DM);
    const double rs = 1.0 / sqrt(v2[1] * (1.0 / DM) - mu * mu + EPSD);
#pragma unroll
    for (int c = 0; c < 8; ++c) {
        const int d = d0 + c;
        g_s[d] = (h[c] - mu) * rs * (double)lng[7 * DM + d] + (double)lnb[7 * DM + d];
    }
}

// ---------------- kernel: left/right GEMVs + gelu + product (fp64) ----------
__global__ __launch_bounds__(128) void k_pass5(const float* __restrict__ Wl,
                                               const float* __restrict__ bl,
                                               const float* __restrict__ Wr,
                                               const float* __restrict__ br) {
    __shared__ double s_red[4 * 2];
    const int j = blockIdx.x;
    const int tid = threadIdx.x;
    double v2[2] = {0.0, 0.0};
    const float* wl = Wl + (size_t)j * DM;
    const float* wr = Wr + (size_t)j * DM;
    for (int d = tid; d < DM; d += 128) {
        const double s = g_s[d];
        v2[0] += s * (double)wl[d];
        v2[1] += s * (double)wr[d];
    }
    block_reduce_d<2>(v2, s_red);
    if (tid == 0) {
        const double left = v2[0] + (double)bl[j];
        double right = v2[1] + (double)br[j];
        right = 0.5 * right * (1.0 + erf(right * 0.7071067811865475244));  // exact gelu
        g_v[j] = left * right;
    }
}

// ---------------- kernel: LN over DFF (fp64) ----------------
__global__ __launch_bounds__(512) void k_pass6a(const float* __restrict__ og,
                                                const float* __restrict__ ob) {
    __shared__ double s_red[16 * 2];
    const int tid = threadIdx.x;
    double v2[2] = {0.0, 0.0};
    for (int jj = tid; jj < DFF; jj += 512) {
        const double x = g_v[jj];
        v2[0] += x; v2[1] += x * x;
    }
    block_reduce_d<2>(v2, s_red);
    const double mu = v2[0] * (1.0 / DFF);
    const double rs = 1.0 / sqrt(v2[1] * (1.0 / DFF) - mu * mu + EPSD);
    for (int jj = tid; jj < DFF; jj += 512)
        g_u[jj] = (g_v[jj] - mu) * rs * (double)og[jj] + (double)ob[jj];
}

// ---------------- kernel: final projection GEMV (fp64) ----------------
__global__ __launch_bounds__(128) void k_pass6b(const float* __restrict__ Wp,
                                                const float* __restrict__ bp,
                                                float* __restrict__ out) {
    __shared__ double s_red[4 * 1];
    const int d = blockIdx.x;
    const int tid = threadIdx.x;
    double acc[1] = {0.0};
    const float* wp = Wp + (size_t)d * DFF;
    for (int jj = tid; jj < DFF; jj += 128) acc[0] += g_u[jj] * (double)wp[jj];
    block_reduce_d<1>(acc, s_red);
    if (tid == 0) out[d] = (float)(acc[0] + (double)bp[d]);
}

// ---------------- launcher ----------------
extern "C" void kernel_launch(void* const* d_in, const int* in_sizes, int n_in,
                              void* d_out, int out_size) {
    const float* x      = (const float*)d_in[0];
    const float* Wg     = (const float*)d_in[1];
    const float* bgates = (const float*)d_in[2];
    // d_in[3] = Wr_gates: multiplies zero initial state -> unused
    const float* lng    = (const float*)d_in[4];
    const float* lnb    = (const float*)d_in[5];
    const float* lnoutg = (const float*)d_in[6];
    const float* lnoutb = (const float*)d_in[7];
    const float* Wl     = (const float*)d_in[8];
    const float* bl     = (const float*)d_in[9];
    const float* Wr     = (const float*)d_in[10];
    const float* br     = (const float*)d_in[11];
    const float* Wp     = (const float*)d_in[12];
    const float* bp     = (const float*)d_in[13];
    float* out = (float*)d_out;

    k_zero<<<8, 512>>>();
    k_silu<<<(MROWS * (size_t)DM) / (256 * 4), 256>>>(x);
    k_gemm_oz<<<dim3(64, 8, 8), 256>>>(Wg);   // gates o,z via single-term TF32
    k_gemm_if<<<dim3(64, 8, 8), 256>>>(Wg);   // gates i,f bit-exact scalar
    k_pass2<<<296, 512>>>(bgates, lng, lnb);
    k_redsum<<<DM / 32, 32>>>();
    k_pass3<<<296, 512>>>(lng, lnb);
    k_pass4<<<1, 512>>>(lng, lnb);
    k_pass5<<<DFF, 128>>>(Wl, bl, Wr, br);
    k_pass6a<<<1, 512>>>(lnoutg, lnoutb);
    k_pass6b<<<DM, 128>>>(Wp, bp, out);
}